// round 12
// baseline (speedup 1.0000x reference)
#include <cuda_runtime.h>
#include <cstdint>

// Problem constants
#define PB   64
#define PS   1024
#define PF   768
#define PH   12
#define PP2  64
#define HEADSZ 4096
#define QKVSTRIDE (PB * PH * HEADSZ)   // 3,145,728

__device__ float g_qkv[3LL * QKVSTRIDE];
__device__ float g_o[4096LL * PF];

// ---------------------------------------------------------------------------
// PTX helpers
// ---------------------------------------------------------------------------
__device__ __forceinline__ void cp16(void* s, const void* g) {
    unsigned sa = (unsigned)__cvta_generic_to_shared(s);
    asm volatile("cp.async.cg.shared.global [%0], [%1], 16;\n" :: "r"(sa), "l"(g));
}
__device__ __forceinline__ void cp_commit() { asm volatile("cp.async.commit_group;\n"); }
template <int N>
__device__ __forceinline__ void cp_wait() { asm volatile("cp.async.wait_group %0;\n" :: "n"(N)); }

__device__ __forceinline__ void mma_tf32(float* c, const unsigned* a, const unsigned* b) {
    asm volatile(
        "mma.sync.aligned.m16n8k8.row.col.f32.tf32.tf32.f32 "
        "{%0,%1,%2,%3}, {%4,%5,%6,%7}, {%8,%9}, {%0,%1,%2,%3};"
        : "+f"(c[0]), "+f"(c[1]), "+f"(c[2]), "+f"(c[3])
        : "r"(a[0]), "r"(a[1]), "r"(a[2]), "r"(a[3]), "r"(b[0]), "r"(b[1]));
}

// ldmatrix x4 on 32-bit data viewed as b16 pairs: thread gets one fp32/matrix.
__device__ __forceinline__ void ldsm4(unsigned* r, unsigned saddr) {
    asm volatile("ldmatrix.sync.aligned.m8n8.x4.shared.b16 {%0,%1,%2,%3}, [%4];"
                 : "=r"(r[0]), "=r"(r[1]), "=r"(r[2]), "=r"(r[3]) : "r"(saddr));
}

// Fine-grained streaming tail-copy chunk: x[:,64:,:] -> out[:,64:,:]
#define CCHUNK 12288    // float4 per chunk; 960 chunks total
__device__ __forceinline__ void copy_chunk(int cb, const float4* __restrict__ src,
                                           float4* __restrict__ dst, int tid) {
    const int PERB = (PS - PP2) * (PF / 4);        // 184320
    int base = cb * CCHUNK;
    #pragma unroll 4
    for (int t = tid; t < CCHUNK; t += 256) {
        int i = base + t;
        int b = i / PERB;
        int rem = i - b * PERB;
        long long off = (long long)b * (PS * (PF / 4)) + PP2 * (PF / 4) + rem;
        __stcs(dst + off, __ldcs(src + off));
    }
}

// ---------------------------------------------------------------------------
// TF32 mma.sync GEMM, ldmatrix fragment loads. Block tile 128x128, BK=32,
// 3-stage cp.async, one __syncthreads per iter. 8 warps 2(M)x4(N), warp 64x32.
// MODE 0: C[4096,2304] = Xw @ [Wq;Wk;Wv]^T + bias -> g_qkv; 1D grid:
//         blocks [0,576) GEMM, [576,1536) appended tail-copy chunks.
// MODE 1: C[4096, 768] = O @ Wo^T + bo -> d_out (s < 64); 2D grid (32,6).
// ---------------------------------------------------------------------------
#define BK   32
#define LDK  36                         // 32 + 4: LDSM rows stride 9*16B -> conflict-free
#define STAGEF ((128 + 128) * LDK)      // 9216 floats / stage
#define NSTG 3
#define DSMEM  (NSTG * STAGEF * 4)      // 110592 B -> 2 CTAs/SM
#define NKI  (PF / BK)                  // 24

template <int MODE>
__global__ void __launch_bounds__(256, 2) tc_gemm(
    const float* __restrict__ A,
    const float* __restrict__ W0, const float* __restrict__ W1, const float* __restrict__ W2,
    const float* __restrict__ b0, const float* __restrict__ b1, const float* __restrict__ b2,
    float* __restrict__ Cout)
{
    extern __shared__ float sm[];
    const int tid = threadIdx.x;

    int bx, ny;
    if (MODE == 0) {
        int bid = blockIdx.x;
        if (bid >= 576) {
            // appended copy chunks: fill slots as gemm blocks retire
            copy_chunk(bid - 576, (const float4*)A, (float4*)Cout, tid);
            return;
        }
        bx = bid & 31;
        ny = bid >> 5;
    } else {
        bx = blockIdx.x;
        ny = blockIdx.y;
    }

    const int wid  = tid >> 5;
    const int lane = tid & 31;
    const int wm   = wid >> 2;           // 0..1
    const int wn   = wid & 3;            // 0..3
    const int g    = lane >> 2;          // 0..7
    const int t4   = lane & 3;           // 0..3
    const int rl   = (lane & 7) | (((lane >> 3) & 1) << 3);  // ldsm row
    const int cl   = ((lane >> 4) & 1) * 4;                  // ldsm col

    const int m0 = bx * 128;
    const float* W; const float* bias; int nbw; int wsel = 0;
    if (MODE == 0) {
        wsel = ny / 6;
        nbw  = (ny % 6) * 128;
        W    = (wsel == 0) ? W0 : (wsel == 1 ? W1 : W2);
        bias = (wsel == 0) ? b0 : (wsel == 1 ? b1 : b2);
    } else {
        W = W0; bias = b0; nbw = ny * 128;
    }
    const float* Ap = (MODE == 0) ? A : g_o;

    // Stage loader: A 128x32 + B 128x32, 4+4 cp16 per thread
    auto load_stage = [&](int buf, int k0) {
        float* As = sm + buf * STAGEF;
        float* Bs = As + 128 * LDK;
        #pragma unroll
        for (int p = 0; p < 4; p++) {
            int idx = tid + p * 256;
            int r = idx >> 3, c4 = (idx & 7) * 4;
            int gm = m0 + r;
            const float* ga = (MODE == 0)
                ? Ap + ((long long)(gm >> 6) * PS + (gm & 63)) * PF + k0 + c4
                : Ap + (long long)gm * PF + k0 + c4;
            cp16(&As[r * LDK + c4], ga);
        }
        #pragma unroll
        for (int p = 0; p < 4; p++) {
            int idx = tid + p * 256;
            int r = idx >> 3, c4 = (idx & 7) * 4;
            const float* gb = W + (long long)(nbw + r) * PF + k0 + c4;
            cp16(&Bs[r * LDK + c4], gb);
        }
    };

    float acc[4][4][4];
    #pragma unroll
    for (int mi = 0; mi < 4; mi++)
        #pragma unroll
        for (int ni = 0; ni < 4; ni++)
            #pragma unroll
            for (int q = 0; q < 4; q++) acc[mi][ni][q] = 0.0f;

    load_stage(0, 0);
    cp_commit();
    load_stage(1, BK);
    cp_commit();

    const unsigned sm_sa = (unsigned)__cvta_generic_to_shared(sm);

    int buf = 0;
    for (int i = 0; i < NKI; i++) {
        if (i < NKI - 1) { cp_wait<1>(); } else { cp_wait<0>(); }
        __syncthreads();
        if (i + 2 < NKI) {
            int lb = buf + 2; if (lb >= NSTG) lb -= NSTG;
            load_stage(lb, (i + 2) * BK);
            cp_commit();
        }

        // ldmatrix base addresses for this warp (bytes, shared space)
        const unsigned stage_sa = sm_sa + buf * (STAGEF * 4);
        const unsigned a_sa = stage_sa + ((wm * 64 + rl) * LDK + cl) * 4;
        const unsigned b_sa = stage_sa + ((128 + wn * 32 + rl) * LDK + cl) * 4;

        #pragma unroll
        for (int kk = 0; kk < BK; kk += 8) {
            unsigned af[4][4];
            #pragma unroll
            for (int mi = 0; mi < 4; mi++)
                ldsm4(af[mi], a_sa + (mi * 16 * LDK + kk) * 4);
            unsigned bf[4][2];
            #pragma unroll
            for (int np = 0; np < 2; np++) {
                unsigned t[4];
                ldsm4(t, b_sa + (np * 16 * LDK + kk) * 4);
                bf[2 * np][0]     = t[0];
                bf[2 * np + 1][0] = t[1];
                bf[2 * np][1]     = t[2];
                bf[2 * np + 1][1] = t[3];
            }
            #pragma unroll
            for (int mi = 0; mi < 4; mi++)
                #pragma unroll
                for (int ni = 0; ni < 4; ni++)
                    mma_tf32(acc[mi][ni], af[mi], bf[ni]);
        }

        buf++; if (buf >= NSTG) buf -= NSTG;
    }

    // Bias per ni (float2, col pair this thread owns)
    float2 bfrag[4];
    #pragma unroll
    for (int ni = 0; ni < 4; ni++)
        bfrag[ni] = *reinterpret_cast<const float2*>(bias + nbw + wn * 32 + ni * 8 + t4 * 2);

    // Epilogue: direct global float2 stores from accumulators
    #pragma unroll
    for (int mi = 0; mi < 4; mi++) {
        #pragma unroll
        for (int half = 0; half < 2; half++) {
            int gm = m0 + wm * 64 + mi * 16 + g + half * 8;
            int bb_ = gm >> 6, ss_ = gm & 63;
            #pragma unroll
            for (int ni = 0; ni < 4; ni++) {
                int n = nbw + wn * 32 + ni * 8 + t4 * 2;
                float2 v;
                v.x = acc[mi][ni][half * 2 + 0] + bfrag[ni].x;
                v.y = acc[mi][ni][half * 2 + 1] + bfrag[ni].y;
                if (MODE == 0) {
                    int h = n >> 6, d = n & 63;
                    float* dst = g_qkv + (long long)wsel * QKVSTRIDE
                               + (long long)(bb_ * PH + h) * HEADSZ + ss_ * 64 + d;
                    *reinterpret_cast<float2*>(dst) = v;
                } else {
                    float* dst = Cout + ((long long)bb_ * PS + ss_) * PF + n;
                    *reinterpret_cast<float2*>(dst) = v;
                }
            }
        }
    }
}

// ---------------------------------------------------------------------------
// Attention, one block per (b,h). 64x64 q,k,v tiles in smem.
// ---------------------------------------------------------------------------
__global__ void __launch_bounds__(256) attn_kernel() {
    __shared__ float sq[64 * 64];
    __shared__ float sk[64 * 64];
    __shared__ float ss[64 * 64];

    const int tid = threadIdx.x;
    const int b = blockIdx.x / PH;
    const int h = blockIdx.x % PH;
    const float* qg = g_qkv + (long long)(b * PH + h) * HEADSZ;
    const float* kg = qg + (long long)QKVSTRIDE;
    const float* vg = kg + (long long)QKVSTRIDE;
    const int lane = tid & 31;

    for (int t = tid; t < 1024; t += 256)
        reinterpret_cast<float4*>(sq)[t] = reinterpret_cast<const float4*>(qg)[t];
    for (int t = tid; t < 1024; t += 256) {
        int j = t >> 4, d4 = (t & 15) * 4;
        float4 v = reinterpret_cast<const float4*>(kg)[t];
        *reinterpret_cast<float4*>(&sk[j * 64 + (d4 ^ ((j & 7) << 3))]) = v;
    }
    __syncthreads();

    #pragma unroll
    for (int t = 0; t < 16; t++) {
        int idx = tid + (t << 8);
        int i = idx >> 6, j = idx & 63;
        int sw = (j & 7) << 3;
        float s = 0.f;
        #pragma unroll
        for (int dd = 0; dd < 64; dd += 4) {
            float4 q4 = *reinterpret_cast<const float4*>(&sq[i * 64 + dd]);
            float4 k4 = *reinterpret_cast<const float4*>(&sk[j * 64 + (dd ^ sw)]);
            s += q4.x * k4.x + q4.y * k4.y + q4.z * k4.z + q4.w * k4.w;
        }
        ss[idx] = s * 0.125f;
    }
    __syncthreads();

    {
        int w = tid >> 5;
        #pragma unroll
        for (int rr = 0; rr < 8; rr++) {
            int i = w * 8 + rr;
            float x0 = ss[i * 64 + lane];
            float x1 = ss[i * 64 + 32 + lane];
            float m = fmaxf(x0, x1);
            #pragma unroll
            for (int o = 16; o; o >>= 1) m = fmaxf(m, __shfl_xor_sync(0xffffffffu, m, o));
            float e0 = __expf(x0 - m), e1 = __expf(x1 - m);
            float sum = e0 + e1;
            #pragma unroll
            for (int o = 16; o; o >>= 1) sum += __shfl_xor_sync(0xffffffffu, sum, o);
            float inv = 1.0f / sum;
            ss[i * 64 + lane]      = e0 * inv;
            ss[i * 64 + 32 + lane] = e1 * inv;
        }
    }
    __syncthreads();

    for (int t = tid; t < 1024; t += 256)
        reinterpret_cast<float4*>(sq)[t] = reinterpret_cast<const float4*>(vg)[t];
    __syncthreads();

    #pragma unroll
    for (int t = 0; t < 4; t++) {
        int gidx = tid + (t << 8);
        int i  = gidx >> 4;
        int d4 = (gidx & 15) * 4;
        float ox = 0.f, oy = 0.f, oz = 0.f, ow = 0.f;
        #pragma unroll 16
        for (int j = 0; j < 64; j++) {
            float a = ss[i * 64 + j];
            float4 v4 = *reinterpret_cast<const float4*>(&sq[j * 64 + d4]);
            ox += a * v4.x; oy += a * v4.y; oz += a * v4.z; ow += a * v4.w;
        }
        float4 o4; o4.x = ox; o4.y = oy; o4.z = oz; o4.w = ow;
        *reinterpret_cast<float4*>(&g_o[(long long)(b * 64 + i) * PF + h * 64 + d4]) = o4;
    }
}

// ---------------------------------------------------------------------------
extern "C" void kernel_launch(void* const* d_in, const int* in_sizes, int n_in,
                              void* d_out, int out_size) {
    const float* x  = (const float*)d_in[0];
    const float* Wq = (const float*)d_in[1];
    const float* bq = (const float*)d_in[2];
    const float* Wk = (const float*)d_in[3];
    const float* bk = (const float*)d_in[4];
    const float* Wv = (const float*)d_in[5];
    const float* bv = (const float*)d_in[6];
    const float* Wo = (const float*)d_in[7];
    const float* bo = (const float*)d_in[8];
    float* out = (float*)d_out;

    cudaFuncSetAttribute(tc_gemm<0>, cudaFuncAttributeMaxDynamicSharedMemorySize, DSMEM);
    cudaFuncSetAttribute(tc_gemm<1>, cudaFuncAttributeMaxDynamicSharedMemorySize, DSMEM);

    // 1) QKV projection (+bias) into g_qkv; 960 tail-copy chunks appended
    //    AFTER all 576 gemm blocks (backfill as gemm retires -> overlap)
    tc_gemm<0><<<576 + 960, 256, DSMEM>>>(x, Wq, Wk, Wv, bq, bk, bv, out);

    // 2) attention per (b,h), pure
    attn_kernel<<<PB * PH, 256>>>();

    // 3) output projection (+bo) into d_out[:, :64, :], pure
    tc_gemm<1><<<dim3(32, 6), 256, DSMEM>>>(nullptr, Wo, nullptr, nullptr,
                                            bo, nullptr, nullptr, out);
}